// round 15
// baseline (speedup 1.0000x reference)
#include <cuda_runtime.h>
#include <cuda_fp16.h>
#include <math.h>
#include <stdint.h>

// Problem dims: n = 8192 sequences, V=25 tokens, D=256, H=8, HD=32
#define NSEQ  8192
#define M_TOT 204800        // 8192*25, divisible by 128 -> 1600 M-tiles

// ---------------- device scratch (allocation-free: __device__ globals) -------
__device__ __half  g_a[(size_t)M_TOT * 256];    // attn output (fp16)
__device__ __half  g_qkv[(size_t)M_TOT * 768];  // qkv out (fp16)
__device__ __half  g_h[(size_t)M_TOT * 1024];   // ffn hidden (fp16)
__device__ float2  g_stats[M_TOT];              // per-row (mean, rstd)
// transposed weights: [qkv 768x256 | proj 256x256 | ffn1 1024x256 | ffn2 256x1024]
#define WOFF_QKV  0
#define WOFF_PROJ 196608
#define WOFF_F1   262144
#define WOFF_F2   524288
__device__ __half g_w[786432];

// ---------------- PTX helpers ------------------------------------------------
__device__ __forceinline__ uint32_t smem_u32(const void* p) {
    uint32_t a;
    asm("{ .reg .u64 t; cvta.to.shared.u64 t, %1; cvt.u32.u64 %0, t; }" : "=r"(a) : "l"(p));
    return a;
}
#define CP_COMMIT() asm volatile("cp.async.commit_group;" ::: "memory")
#define CP_WAIT1()  asm volatile("cp.async.wait_group 1;" ::: "memory")
#define CP_WAIT0()  asm volatile("cp.async.wait_group 0;" ::: "memory")
__device__ __forceinline__ void cpa16(uint32_t dst, const void* src) {
    asm volatile("cp.async.cg.shared.global [%0], [%1], 16;" :: "r"(dst), "l"(src));
}
__device__ __forceinline__ void ldm_x4(uint32_t& r0, uint32_t& r1, uint32_t& r2, uint32_t& r3, uint32_t addr) {
    asm volatile("ldmatrix.sync.aligned.m8n8.x4.shared.b16 {%0,%1,%2,%3}, [%4];"
                 : "=r"(r0), "=r"(r1), "=r"(r2), "=r"(r3) : "r"(addr));
}
__device__ __forceinline__ void ldm_x4_t(uint32_t& r0, uint32_t& r1, uint32_t& r2, uint32_t& r3, uint32_t addr) {
    asm volatile("ldmatrix.sync.aligned.m8n8.x4.trans.shared.b16 {%0,%1,%2,%3}, [%4];"
                 : "=r"(r0), "=r"(r1), "=r"(r2), "=r"(r3) : "r"(addr));
}
__device__ __forceinline__ void mma_fp16(float* d, const uint32_t* a, uint32_t b0, uint32_t b1) {
    asm volatile("mma.sync.aligned.m16n8k16.row.col.f32.f16.f16.f32 "
                 "{%0,%1,%2,%3},{%4,%5,%6,%7},{%8,%9},{%0,%1,%2,%3};"
                 : "+f"(d[0]), "+f"(d[1]), "+f"(d[2]), "+f"(d[3])
                 : "r"(a[0]), "r"(a[1]), "r"(a[2]), "r"(a[3]), "r"(b0), "r"(b1));
}
__device__ __forceinline__ float warp_sum(float v) {
#pragma unroll
    for (int o = 16; o > 0; o >>= 1) v += __shfl_xor_sync(0xffffffffu, v, o);
    return v;
}
__device__ __forceinline__ float hsq(uint32_t u) {
    float2 f = __half22float2(*(__half2*)&u);
    return f.x * f.x + f.y * f.y;
}

// ---------------- weight prep: transpose to [N x K] fp16 ---------------------
__global__ void prep_w_kernel(const float* __restrict__ qkvw, const float* __restrict__ projw,
                              const float* __restrict__ f1w, const float* __restrict__ f2w) {
    int idx = blockIdx.x * 256 + threadIdx.x;
    if (idx >= 786432) return;
    const float* src; int K, N, local;
    if (idx < WOFF_PROJ)    { src = qkvw;  K = 256;  N = 768;  local = idx; }
    else if (idx < WOFF_F1) { src = projw; K = 256;  N = 256;  local = idx - WOFF_PROJ; }
    else if (idx < WOFF_F2) { src = f1w;   K = 256;  N = 1024; local = idx - WOFF_F1; }
    else                    { src = f2w;   K = 1024; N = 256;  local = idx - WOFF_F2; }
    int n = local / K, k = local % K;
    g_w[idx] = __float2half_rn(src[(size_t)k * N + n]);
}

// ---------------- LN stats: one warp per row -> (mean, rstd) -----------------
__global__ void __launch_bounds__(256) ln_stats_kernel(const float* __restrict__ in) {
    int row = blockIdx.x * 8 + (threadIdx.x >> 5);
    int lane = threadIdx.x & 31;
    const float4* rp4 = (const float4*)(in + (size_t)row * 256);
    float4 a = rp4[lane], b = rp4[lane + 32];
    float s1 = a.x + a.y + a.z + a.w + b.x + b.y + b.z + b.w;
    float s2 = a.x*a.x + a.y*a.y + a.z*a.z + a.w*a.w + b.x*b.x + b.y*b.y + b.z*b.z + b.w*b.w;
    s1 = warp_sum(s1); s2 = warp_sum(s2);
    if (lane == 0) {
        float mean = s1 * (1.f / 256.f);
        float var = s2 * (1.f / 256.f) - mean * mean;
        g_stats[row] = make_float2(mean, rsqrtf(var + 1e-5f));
    }
}

// ---------------- B-tile loader (128 n-rows x 64 k, fp16, SW128) -------------
__device__ __forceinline__ void load_btile(uint32_t base,
    const __half* __restrict__ B, int kk, int n0, int tid)
{
#pragma unroll
    for (int i = 0; i < 8; i++) {
        int idx = tid + i * 128;
        int r = idx >> 3, c = idx & 7;
        uint32_t off = (uint32_t)(r * 128 + c * 16);
        uint32_t sw = off ^ ((uint32_t)(r & 7) << 4);
        cpa16(base + sw, B + (size_t)(n0 + r) * 256 + kk + c * 8);
    }
}

// ---------------- LN-fused GEMM (K=256): C = LN(A32) @ Wt^T ------------------
// A resident in smem (4 swizzled 16KB k-blocks, 64KB), built in prologue from
// raw fp32 input + precomputed stats. Mainloop streams B only (3x16KB stages).
#define LNG_SMEM (65536 + 3 * 16384)    // 114688 B = 112KB

template<bool GELU>
__global__ void __launch_bounds__(128, 2) ln_gemm(
    const float* __restrict__ A32, int woff,
    const float* __restrict__ lng, const float* __restrict__ lnb,
    const float* __restrict__ bias, int Ntot, __half* __restrict__ outH)
{
    extern __shared__ char smem[];
    uint32_t sb = smem_u32(smem);
    const int tid = threadIdx.x, wid = tid >> 5, lane = tid & 31;
    const int wm = wid & 1, wn = wid >> 1;
    const int m0 = blockIdx.y * 128, n0 = blockIdx.x * 128;
    const __half* W = g_w + woff;
    const uint32_t sbB = sb + 65536;

    // B prefetch first (overlaps A prologue)
    load_btile(sbB,         W, 0,  n0, tid); CP_COMMIT();
    load_btile(sbB + 16384, W, 64, n0, tid); CP_COMMIT();

    // A prologue: fp32 -> LN -> fp16 swizzled k-blocks
#pragma unroll 8
    for (int i = 0; i < 64; i++) {
        int idx = tid + i * 128;            // 0..8191 over 128 rows x 64 float4
        int r = idx >> 6, j = idx & 63;
        float4 xv = ((const float4*)(A32 + (size_t)(m0 + r) * 256))[j];
        float2 st = g_stats[m0 + r];
        float4 gg = ((const float4*)lng)[j];
        float4 bb = ((const float4*)lnb)[j];
        float y0 = (xv.x - st.x) * st.y * gg.x + bb.x;
        float y1 = (xv.y - st.x) * st.y * gg.y + bb.y;
        float y2 = (xv.z - st.x) * st.y * gg.z + bb.z;
        float y3 = (xv.w - st.x) * st.y * gg.w + bb.w;
        __half2 h01 = __floats2half2_rn(y0, y1);
        __half2 h23 = __floats2half2_rn(y2, y3);
        int c = 4 * j;                       // column 0..252
        int kt = c >> 6, col = c & 63;
        uint32_t off = (uint32_t)(r * 128 + col * 2);
        uint32_t sw = off ^ ((uint32_t)(r & 7) << 4);
        *(uint2*)(smem + kt * 16384 + sw) = make_uint2(*(uint32_t*)&h01, *(uint32_t*)&h23);
    }

    float acc[4][8][4];
#pragma unroll
    for (int i = 0; i < 4; i++)
#pragma unroll
        for (int j = 0; j < 8; j++)
#pragma unroll
            for (int kq = 0; kq < 4; kq++) acc[i][j][kq] = 0.f;

    const int grp = lane >> 3, lr = lane & 7;
    const int a_row_b = wm * 64 + (grp & 1) * 8 + lr;
    const int a_kb    = (grp >> 1) * 16;
    const int b_row_b = wn * 64 + (grp >> 1) * 8 + lr;
    const int b_kb    = (grp & 1) * 16;

#pragma unroll
    for (int kt = 0; kt < 4; kt++) {
        const int s = kt % 3;
        if (kt == 3) { CP_WAIT0(); } else { CP_WAIT1(); }
        __syncthreads();     // first iter also publishes A prologue
        if (kt + 2 < 4)
            load_btile(sbB + ((kt + 2) % 3) * 16384, W, (kt + 2) * 64, n0, tid);
        CP_COMMIT();

        const uint32_t aBase = sb + kt * 16384;
        const uint32_t bBase = sbB + s * 16384;
#pragma unroll
        for (int ks = 0; ks < 4; ks++) {
            const int kb = ks * 32;
            uint32_t af[4][4];
#pragma unroll
            for (int mf = 0; mf < 4; mf++) {
                int row = a_row_b + mf * 16;
                uint32_t off = (uint32_t)(row * 128 + kb + a_kb);
                uint32_t addr = aBase + (off ^ ((uint32_t)(row & 7) << 4));
                ldm_x4(af[mf][0], af[mf][1], af[mf][2], af[mf][3], addr);
            }
            uint32_t bf[4][4];
#pragma unroll
            for (int np = 0; np < 4; np++) {
                int row = b_row_b + np * 16;
                uint32_t off = (uint32_t)(row * 128 + kb + b_kb);
                uint32_t addr = bBase + (off ^ ((uint32_t)(row & 7) << 4));
                ldm_x4(bf[np][0], bf[np][1], bf[np][2], bf[np][3], addr);
            }
#pragma unroll
            for (int mf = 0; mf < 4; mf++)
#pragma unroll
                for (int nf = 0; nf < 8; nf++)
                    mma_fp16(acc[mf][nf], af[mf], bf[nf >> 1][(nf & 1) * 2], bf[nf >> 1][(nf & 1) * 2 + 1]);
        }
    }

    const int qr = lane >> 2;
    const int qc = (lane & 3) * 2;
#pragma unroll
    for (int mf = 0; mf < 4; mf++) {
#pragma unroll
        for (int nf = 0; nf < 8; nf++) {
            int C = n0 + wn * 64 + nf * 8 + qc;
            float b0 = __ldg(&bias[C]), b1 = __ldg(&bias[C + 1]);
#pragma unroll
            for (int half_ = 0; half_ < 2; half_++) {
                int R = m0 + wm * 64 + mf * 16 + qr + half_ * 8;
                float v0 = acc[mf][nf][half_ * 2 + 0] + b0;
                float v1 = acc[mf][nf][half_ * 2 + 1] + b1;
                if (GELU) {
                    const float is2 = 0.70710678118654752f;
                    v0 = 0.5f * v0 * (1.0f + erff(v0 * is2));
                    v1 = 0.5f * v1 * (1.0f + erff(v1 * is2));
                }
                *(__half2*)&outH[(size_t)R * Ntot + C] = __floats2half2_rn(v0, v1);
            }
        }
    }
}

// ---------------- plain HMMA GEMM (fp16 in): proj / ffn2 ---------------------
#define ST_SZ   32768
#define GEMM_SMEM (3 * ST_SZ)

__device__ __forceinline__ void load_tile(uint32_t stage_base,
    const __half* __restrict__ A, const __half* __restrict__ B,
    int K, int kk, int m0, int n0, int tid)
{
    uint32_t aB = stage_base;
    uint32_t bB = stage_base + 16384;
#pragma unroll
    for (int i = 0; i < 8; i++) {
        int idx = tid + i * 128;
        int r = idx >> 3, c = idx & 7;
        uint32_t off = (uint32_t)(r * 128 + c * 16);
        uint32_t sw = off ^ ((uint32_t)(r & 7) << 4);
        cpa16(aB + sw, A + (size_t)(m0 + r) * K + kk + c * 8);
    }
#pragma unroll
    for (int i = 0; i < 8; i++) {
        int idx = tid + i * 128;
        int r = idx >> 3, c = idx & 7;
        uint32_t off = (uint32_t)(r * 128 + c * 16);
        uint32_t sw = off ^ ((uint32_t)(r & 7) << 4);
        cpa16(bB + sw, B + (size_t)(n0 + r) * K + kk + c * 8);
    }
}

template<int K, bool RESID>
__global__ void __launch_bounds__(128, 2) gemm_mma(
    const __half* __restrict__ A, int woff,
    const float* __restrict__ bias, int Ntot,
    float* __restrict__ outF, const float* __restrict__ resid)
{
    extern __shared__ char smem[];
    uint32_t sb = smem_u32(smem);
    const int tid = threadIdx.x, wid = tid >> 5, lane = tid & 31;
    const int wm = wid & 1, wn = wid >> 1;
    const int m0 = blockIdx.y * 128, n0 = blockIdx.x * 128;
    constexpr int NT = K >> 6;
    const __half* W = g_w + woff;

    float acc[4][8][4];
#pragma unroll
    for (int i = 0; i < 4; i++)
#pragma unroll
        for (int j = 0; j < 8; j++)
#pragma unroll
            for (int kq = 0; kq < 4; kq++) acc[i][j][kq] = 0.f;

    load_tile(sb,         A, W, K, 0,  m0, n0, tid); CP_COMMIT();
    load_tile(sb + ST_SZ, A, W, K, 64, m0, n0, tid); CP_COMMIT();

    const int grp = lane >> 3, lr = lane & 7;
    const int a_row_b = wm * 64 + (grp & 1) * 8 + lr;
    const int a_kb    = (grp >> 1) * 16;
    const int b_row_b = wn * 64 + (grp >> 1) * 8 + lr;
    const int b_kb    = (grp & 1) * 16;

#pragma unroll
    for (int kt = 0; kt < NT; kt++) {
        const int s = kt % 3;
        if (kt + 1 == NT) { CP_WAIT0(); } else { CP_WAIT1(); }
        __syncthreads();
        if (kt + 2 < NT)
            load_tile(sb + ((kt + 2) % 3) * ST_SZ, A, W, K, (kt + 2) * 64, m0, n0, tid);
        CP_COMMIT();

        const uint32_t aBase = sb + s * ST_SZ;
        const uint32_t bBase = aBase + 16384;
#pragma unroll
        for (int ks = 0; ks < 4; ks++) {
            const int kb = ks * 32;
            uint32_t af[4][4];
#pragma unroll
            for (int mf = 0; mf < 4; mf++) {
                int row = a_row_b + mf * 16;
                uint32_t off = (uint32_t)(row * 128 + kb + a_kb);
                uint32_t addr = aBase + (off ^ ((uint32_t)(row & 7) << 4));
                ldm_x4(af[mf][0], af[mf][1], af[mf][2], af[mf][3], addr);
            }
            uint32_t bf[4][4];
#pragma unroll
            for (int np = 0; np < 4; np++) {
                int row = b_row_b + np * 16;
                uint32_t off = (uint32_t)(row * 128 + kb + b_kb);
                uint32_t addr = bBase + (off ^ ((uint32_t)(row & 7) << 4));
                ldm_x4(bf[np][0], bf[np][1], bf[np][2], bf[np][3], addr);
            }
#pragma unroll
            for (int mf = 0; mf < 4; mf++)
#pragma unroll
                for (int nf = 0; nf < 8; nf++)
                    mma_fp16(acc[mf][nf], af[mf], bf[nf >> 1][(nf & 1) * 2], bf[nf >> 1][(nf & 1) * 2 + 1]);
        }
    }

    const int qr = lane >> 2;
    const int qc = (lane & 3) * 2;
#pragma unroll
    for (int mf = 0; mf < 4; mf++) {
#pragma unroll
        for (int nf = 0; nf < 8; nf++) {
            int C = n0 + wn * 64 + nf * 8 + qc;
            float b0 = __ldg(&bias[C]), b1 = __ldg(&bias[C + 1]);
#pragma unroll
            for (int half_ = 0; half_ < 2; half_++) {
                int R = m0 + wm * 64 + mf * 16 + qr + half_ * 8;
                float v0 = acc[mf][nf][half_ * 2 + 0] + b0;
                float v1 = acc[mf][nf][half_ * 2 + 1] + b1;
                size_t gidx = (size_t)R * Ntot + C;
                if (RESID) {
                    float2 rv = *(const float2*)&resid[gidx];
                    v0 += rv.x; v1 += rv.y;
                }
                *(float2*)&outF[gidx] = make_float2(v0, v1);
            }
        }
    }
}

// ---------------- tensor-core attention: CTA per sequence, warp = head -------
#define ATTN_SMEM 49152
__device__ __forceinline__ uint32_t swz(int row, int byte_) {
    return (uint32_t)((row * 64 + byte_) ^ ((row & 3) << 4));
}
__global__ void __launch_bounds__(256, 2) attn_kernel(const float* __restrict__ logit_scale) {
    extern __shared__ char smem[];
    uint32_t sb = smem_u32(smem);
    const int tid = threadIdx.x, hd = tid >> 5, lane = tid & 31;
    const size_t n = blockIdx.x;

#pragma unroll
    for (int i = 0; i < 12; i++) {
        int idx = tid + i * 256;
        int c16 = idx & 3, h = (idx >> 2) & 7, r = (idx >> 5) & 31, w = idx >> 10;
        uint32_t dst = sb + (uint32_t)(h * 3 + w) * 2048 + swz(r, c16 * 16);
        if (r < 25) {
            const __half* src = g_qkv + (n * 25 + r) * 768 + w * 256 + h * 32 + c16 * 8;
            uint4 v = *(const uint4*)src;
            asm volatile("st.shared.v4.b32 [%0], {%1,%2,%3,%4};" :: "r"(dst), "r"(v.x), "r"(v.y), "r"(v.z), "r"(v.w));
        } else {
            asm volatile("st.shared.v4.b32 [%0], {%1,%1,%1,%1};" :: "r"(dst), "r"(0u));
        }
    }
    __syncthreads();

    const uint32_t qb = sb + (uint32_t)hd * 3 * 2048;
    const uint32_t kb = qb + 2048;
    const uint32_t vb = qb + 4096;
    const int grp = lane >> 3, lr = lane & 7;
    const int qr = lane >> 2, qc = lane & 3;

    uint32_t af[2][2][4];
#pragma unroll
    for (int mf = 0; mf < 2; mf++)
#pragma unroll
        for (int ks = 0; ks < 2; ks++) {
            int row = mf * 16 + (grp & 1) * 8 + lr;
            uint32_t addr = qb + swz(row, (grp >> 1) * 16 + ks * 32);
            ldm_x4(af[mf][ks][0], af[mf][ks][1], af[mf][ks][2], af[mf][ks][3], addr);
        }
    uint32_t kf[2][2][4];
#pragma unroll
    for (int np = 0; np < 2; np++)
#pragma unroll
        for (int ks = 0; ks < 2; ks++) {
            int row = np * 16 + (grp >> 1) * 8 + lr;
            uint32_t addr = kb + swz(row, (grp & 1) * 16 + ks * 32);
            ldm_x4(kf[np][ks][0], kf[np][ks][1], kf[np][ks][2], kf[np][ks][3], addr);
        }

    float acc[2][4][4];
#pragma unroll
    for (int mf = 0; mf < 2; mf++)
#pragma unroll
        for (int nf = 0; nf < 4; nf++)
#pragma unroll
            for (int u = 0; u < 4; u++) acc[mf][nf][u] = 0.f;
#pragma unroll
    for (int ks = 0; ks < 2; ks++)
#pragma unroll
        for (int mf = 0; mf < 2; mf++)
#pragma unroll
            for (int nf = 0; nf < 4; nf++)
                mma_fp16(acc[mf][nf], af[mf][ks], kf[nf >> 1][ks][(nf & 1) * 2], kf[nf >> 1][ks][(nf & 1) * 2 + 1]);

    const float LOG100 = 4.6051701859880914f;
    const float stot = __expf(fminf(__ldg(&logit_scale[hd]), LOG100)) * 0.17677669529663687f;

    float nqp[4], nkp[4];
#pragma unroll
    for (int i = 0; i < 4; i++) {
        int mf = i >> 1, h2 = i & 1;
        nqp[i] = hsq(af[mf][0][h2]) + hsq(af[mf][0][h2 + 2]) + hsq(af[mf][1][h2]) + hsq(af[mf][1][h2 + 2]);
    }
#pragma unroll
    for (int i = 0; i < 4; i++) {
        int np = i >> 1, t = i & 1;
        nkp[i] = hsq(kf[np][0][2 * t]) + hsq(kf[np][0][2 * t + 1]) + hsq(kf[np][1][2 * t]) + hsq(kf[np][1][2 * t + 1]);
    }
#pragma unroll
    for (int o = 1; o <= 2; o <<= 1) {
#pragma unroll
        for (int i = 0; i < 4; i++) {
            nqp[i] += __shfl_xor_sync(0xffffffffu, nqp[i], o);
            nkp[i] += __shfl_xor_sync(0xffffffffu, nkp[i], o);
        }
    }
    float nqr4[4], nkr4[4];
#pragma unroll
    for (int i = 0; i < 4; i++) {
        nqr4[i] = stot / fmaxf(sqrtf(nqp[i]), 1e-12f);
        nkr4[i] = 1.0f / fmaxf(sqrtf(nkp[i]), 1e-12f);
    }
    float skc[4][2];
#pragma unroll
    for (int nf = 0; nf < 4; nf++)
#pragma unroll
        for (int u = 0; u < 2; u++)
            skc[nf][u] = __shfl_sync(0xffffffffu, nkr4[nf], ((2 * qc + u) & 7) << 2);

#pragma unroll
    for (int mf = 0; mf < 2; mf++)
#pragma unroll
        for (int h2 = 0; h2 < 2; h2++) {
            float sq_ = nqr4[mf * 2 + h2];
            float vals[8];
#pragma unroll
            for (int nf = 0; nf < 4; nf++)
#pragma unroll
                for (int u = 0; u < 2; u++) {
                    float v = acc[mf][nf][h2 * 2 + u] * sq_ * skc[nf][u];
                    if (nf == 3 && (24 + 2 * qc + u) >= 25) v = -1e30f;
                    vals[nf * 2 + u] = v;
                }
            float m = vals[0];
#pragma unroll
            for (int j = 1; j < 8; j++) m = fmaxf(m, vals[j]);
            m = fmaxf(m, __shfl_xor_sync(0xffffffffu, m, 1));
            m = fmaxf(m, __shfl_xor_sync(0xffffffffu, m, 2));
            float s = 0.f;
#pragma unroll
            for (int j = 0; j < 8; j++) { vals[j] = __expf(vals[j] - m); s += vals[j]; }
            s += __shfl_xor_sync(0xffffffffu, s, 1);
            s += __shfl_xor_sync(0xffffffffu, s, 2);
            float inv = 1.0f / s;
#pragma unroll
            for (int nf = 0; nf < 4; nf++)
#pragma unroll
                for (int u = 0; u < 2; u++)
                    acc[mf][nf][h2 * 2 + u] = vals[nf * 2 + u] * inv;
        }

    uint32_t pa[2][2][4];
#pragma unroll
    for (int mf = 0; mf < 2; mf++)
#pragma unroll
        for (int ks = 0; ks < 2; ks++) {
            __half2 h0 = __floats2half2_rn(acc[mf][2 * ks][0], acc[mf][2 * ks][1]);
            __half2 h1 = __floats2half2_rn(acc[mf][2 * ks][2], acc[mf][2 * ks][3]);
            __half2 h2_ = __floats2half2_rn(acc[mf][2 * ks + 1][0], acc[mf][2 * ks + 1][1]);
            __half2 h3 = __floats2half2_rn(acc[mf][2 * ks + 1][2], acc[mf][2 * ks + 1][3]);
            pa[mf][ks][0] = *(uint32_t*)&h0; pa[mf][ks][1] = *(uint32_t*)&h1;
            pa[mf][ks][2] = *(uint32_t*)&h2_; pa[mf][ks][3] = *(uint32_t*)&h3;
        }

    uint32_t vf[2][2][4];
#pragma unroll
    for (int ks = 0; ks < 2; ks++)
#pragma unroll
        for (int np = 0; np < 2; np++) {
            int row = ks * 16 + (grp & 1) * 8 + lr;
            uint32_t addr = vb + swz(row, (grp >> 1) * 16 + np * 32);
            ldm_x4_t(vf[ks][np][0], vf[ks][np][1], vf[ks][np][2], vf[ks][np][3], addr);
        }

    float oacc[2][4][4];
#pragma unroll
    for (int mf = 0; mf < 2; mf++)
#pragma unroll
        for (int nf = 0; nf < 4; nf++)
#pragma unroll
            for (int u = 0; u < 4; u++) oacc[mf][nf][u] = 0.f;
#pragma unroll
    for (int ks = 0; ks < 2; ks++)
#pragma unroll
        for (int mf = 0; mf < 2; mf++)
#pragma unroll
            for (int nf = 0; nf < 4; nf++)
                mma_fp16(oacc[mf][nf], pa[mf][ks], vf[ks][nf >> 1][(nf & 1) * 2], vf[ks][nf >> 1][(nf & 1) * 2 + 1]);

#pragma unroll
    for (int mf = 0; mf < 2; mf++)
#pragma unroll
        for (int h2 = 0; h2 < 2; h2++) {
            int R = mf * 16 + h2 * 8 + qr;
            if (R < 25) {
#pragma unroll
                for (int nf = 0; nf < 4; nf++) {
                    int d = nf * 8 + 2 * qc;
                    __half2 hv = __floats2half2_rn(oacc[mf][nf][h2 * 2], oacc[mf][nf][h2 * 2 + 1]);
                    *(__half2*)&g_a[(n * 25 + R) * 256 + hd * 32 + d] = hv;
                }
            }
        }
}

// ---------------- launch -----------------------------------------------------
extern "C" void kernel_launch(void* const* d_in, const int* in_sizes, int n_in,
                              void* d_out, int out_size)
{
    const float* x           = (const float*)d_in[0];
    const float* ln1_g       = (const float*)d_in[1];
    const float* ln1_b       = (const float*)d_in[2];
    const float* qkv_w       = (const float*)d_in[3];
    const float* qkv_b       = (const float*)d_in[4];
    const float* proj_w      = (const float*)d_in[5];
    const float* proj_b      = (const float*)d_in[6];
    const float* logit_scale = (const float*)d_in[7];
    const float* ln2_g       = (const float*)d_in[8];
    const float* ln2_b       = (const float*)d_in[9];
    const float* ffn_w1      = (const float*)d_in[10];
    const float* ffn_b1      = (const float*)d_in[11];
    const float* ffn_w2      = (const float*)d_in[12];
    const float* ffn_b2      = (const float*)d_in[13];
    float* out = (float*)d_out;

    cudaFuncSetAttribute(ln_gemm<false>, cudaFuncAttributeMaxDynamicSharedMemorySize, LNG_SMEM);
    cudaFuncSetAttribute(ln_gemm<true >, cudaFuncAttributeMaxDynamicSharedMemorySize, LNG_SMEM);
    cudaFuncSetAttribute(gemm_mma<256 ,true>, cudaFuncAttributeMaxDynamicSharedMemorySize, GEMM_SMEM);
    cudaFuncSetAttribute(gemm_mma<1024,true>, cudaFuncAttributeMaxDynamicSharedMemorySize, GEMM_SMEM);
    cudaFuncSetAttribute(attn_kernel, cudaFuncAttributeMaxDynamicSharedMemorySize, ATTN_SMEM);

    __half *ap, *qkvp, *hp;
    cudaGetSymbolAddress((void**)&ap,   g_a);
    cudaGetSymbolAddress((void**)&qkvp, g_qkv);
    cudaGetSymbolAddress((void**)&hp,   g_h);

    // 1) weight transpose -> fp16
    prep_w_kernel<<<3072, 256>>>(qkv_w, proj_w, ffn_w1, ffn_w2);
    // 2) LN1 stats
    ln_stats_kernel<<<M_TOT / 8, 256>>>(x);
    // 3) QKV GEMM with fused LN1 -> g_qkv (fp16)
    ln_gemm<false><<<dim3(6, 1600), 128, LNG_SMEM>>>(
        x, WOFF_QKV, ln1_g, ln1_b, qkv_b, 768, qkvp);
    // 4) attention -> g_a (fp16)
    attn_kernel<<<NSEQ, 256, ATTN_SMEM>>>(logit_scale);
    // 5) proj GEMM + residual(x) -> d_out (xf, fp32)
    gemm_mma<256,true><<<dim3(2, 1600), 128, GEMM_SMEM>>>(
        ap, WOFF_PROJ, proj_b, 256, out, x);
    // 6) LN2 stats on xf
    ln_stats_kernel<<<M_TOT / 8, 256>>>(out);
    // 7) FFN1 GEMM with fused LN2 + GELU -> g_h (fp16)
    ln_gemm<true><<<dim3(8, 1600), 128, LNG_SMEM>>>(
        out, WOFF_F1, ln2_g, ln2_b, ffn_b1, 1024, hp);
    // 8) FFN2 GEMM + residual(xf) -> d_out (final)
    gemm_mma<1024,true><<<dim3(2, 1600), 128, GEMM_SMEM>>>(
        hp, WOFF_F2, ffn_b2, 256, out, out);
}

// round 16
// speedup vs baseline: 1.2031x; 1.2031x over previous
#include <cuda_runtime.h>
#include <cuda_fp16.h>
#include <math.h>
#include <stdint.h>

// Problem dims: n = 8192 sequences, V=25 tokens, D=256, H=8, HD=32
#define NSEQ  8192
#define M_TOT 204800        // 8192*25, divisible by 128 -> 1600 M-tiles

// ---------------- device scratch (allocation-free: __device__ globals) -------
__device__ __half g_a[(size_t)M_TOT * 256];     // activations (fp16)
__device__ __half g_qkv[(size_t)M_TOT * 768];   // qkv out (fp16)
__device__ __half g_h[(size_t)M_TOT * 1024];    // ffn hidden (fp16)
// transposed weights: [qkv 768x256 | proj 256x256 | ffn1 1024x256 | ffn2 256x1024]
#define WOFF_QKV  0
#define WOFF_PROJ 196608
#define WOFF_F1   262144
#define WOFF_F2   524288
__device__ __half g_w[786432];

// ---------------- PTX helpers ------------------------------------------------
__device__ __forceinline__ uint32_t smem_u32(const void* p) {
    uint32_t a;
    asm("{ .reg .u64 t; cvta.to.shared.u64 t, %1; cvt.u32.u64 %0, t; }" : "=r"(a) : "l"(p));
    return a;
}
#define CP_COMMIT() asm volatile("cp.async.commit_group;" ::: "memory")
#define CP_WAIT1()  asm volatile("cp.async.wait_group 1;" ::: "memory")
#define CP_WAIT0()  asm volatile("cp.async.wait_group 0;" ::: "memory")
__device__ __forceinline__ void cpa16(uint32_t dst, const void* src) {
    asm volatile("cp.async.cg.shared.global [%0], [%1], 16;" :: "r"(dst), "l"(src));
}
__device__ __forceinline__ void ldm_x4(uint32_t& r0, uint32_t& r1, uint32_t& r2, uint32_t& r3, uint32_t addr) {
    asm volatile("ldmatrix.sync.aligned.m8n8.x4.shared.b16 {%0,%1,%2,%3}, [%4];"
                 : "=r"(r0), "=r"(r1), "=r"(r2), "=r"(r3) : "r"(addr));
}
__device__ __forceinline__ void ldm_x4_t(uint32_t& r0, uint32_t& r1, uint32_t& r2, uint32_t& r3, uint32_t addr) {
    asm volatile("ldmatrix.sync.aligned.m8n8.x4.trans.shared.b16 {%0,%1,%2,%3}, [%4];"
                 : "=r"(r0), "=r"(r1), "=r"(r2), "=r"(r3) : "r"(addr));
}
__device__ __forceinline__ void mma_fp16(float* d, const uint32_t* a, uint32_t b0, uint32_t b1) {
    asm volatile("mma.sync.aligned.m16n8k16.row.col.f32.f16.f16.f32 "
                 "{%0,%1,%2,%3},{%4,%5,%6,%7},{%8,%9},{%0,%1,%2,%3};"
                 : "+f"(d[0]), "+f"(d[1]), "+f"(d[2]), "+f"(d[3])
                 : "r"(a[0]), "r"(a[1]), "r"(a[2]), "r"(a[3]), "r"(b0), "r"(b1));
}
__device__ __forceinline__ float warp_sum(float v) {
#pragma unroll
    for (int o = 16; o > 0; o >>= 1) v += __shfl_xor_sync(0xffffffffu, v, o);
    return v;
}
__device__ __forceinline__ float hsq(uint32_t u) {
    float2 f = __half22float2(*(__half2*)&u);
    return f.x * f.x + f.y * f.y;
}

// ---------------- weight prep: transpose to [N x K] fp16 ---------------------
__global__ void prep_w_kernel(const float* __restrict__ qkvw, const float* __restrict__ projw,
                              const float* __restrict__ f1w, const float* __restrict__ f2w) {
    int idx = blockIdx.x * 256 + threadIdx.x;
    if (idx >= 786432) return;
    const float* src; int K, N, local;
    if (idx < WOFF_PROJ)    { src = qkvw;  K = 256;  N = 768;  local = idx; }
    else if (idx < WOFF_F1) { src = projw; K = 256;  N = 256;  local = idx - WOFF_PROJ; }
    else if (idx < WOFF_F2) { src = f1w;   K = 256;  N = 1024; local = idx - WOFF_F1; }
    else                    { src = f2w;   K = 1024; N = 256;  local = idx - WOFF_F2; }
    int n = local / K, k = local % K;
    g_w[idx] = __float2half_rn(src[(size_t)k * N + n]);
}

// ---------------- LayerNorm -> fp16: one warp per row, float4 ----------------
__global__ void __launch_bounds__(256) ln_h_kernel(
    const float* __restrict__ in, const float* __restrict__ g, const float* __restrict__ b) {
    int row = blockIdx.x * 8 + (threadIdx.x >> 5);
    int lane = threadIdx.x & 31;
    const float4* rp4 = (const float4*)(in + (size_t)row * 256);
    float4 xv[2];
    xv[0] = rp4[lane]; xv[1] = rp4[lane + 32];
    float s1 = xv[0].x + xv[0].y + xv[0].z + xv[0].w + xv[1].x + xv[1].y + xv[1].z + xv[1].w;
    float s2 = xv[0].x*xv[0].x + xv[0].y*xv[0].y + xv[0].z*xv[0].z + xv[0].w*xv[0].w
             + xv[1].x*xv[1].x + xv[1].y*xv[1].y + xv[1].z*xv[1].z + xv[1].w*xv[1].w;
    s1 = warp_sum(s1); s2 = warp_sum(s2);
    float mean = s1 * (1.f / 256.f);
    float var = s2 * (1.f / 256.f) - mean * mean;
    float rs = rsqrtf(var + 1e-5f);
    __half* op = g_a + (size_t)row * 256;
#pragma unroll
    for (int u = 0; u < 2; u++) {
        int c4 = lane + 32 * u;
        float4 gg = ((const float4*)g)[c4];
        float4 bb = ((const float4*)b)[c4];
        float y0 = (xv[u].x - mean) * rs * gg.x + bb.x;
        float y1 = (xv[u].y - mean) * rs * gg.y + bb.y;
        float y2 = (xv[u].z - mean) * rs * gg.z + bb.z;
        float y3 = (xv[u].w - mean) * rs * gg.w + bb.w;
        __half2 h01 = __floats2half2_rn(y0, y1);
        __half2 h23 = __floats2half2_rn(y2, y3);
        *(uint2*)&op[c4 * 4] = make_uint2(*(uint32_t*)&h01, *(uint32_t*)&h23);
    }
}

// ============== 4-warp GEMM (CTA 128x128): QKV / FFN1 ========================
#define ST_SZ   32768          // per stage: A 16KB + B 16KB
#define GEMM_SMEM (3 * ST_SZ)  // 96KB

__device__ __forceinline__ void load_tile(uint32_t stage_base,
    const __half* __restrict__ A, const __half* __restrict__ B,
    int K, int kk, int m0, int n0, int tid)
{
    uint32_t aB = stage_base;
    uint32_t bB = stage_base + 16384;
#pragma unroll
    for (int i = 0; i < 8; i++) {
        int idx = tid + i * 128;
        int r = idx >> 3, c = idx & 7;
        uint32_t off = (uint32_t)(r * 128 + c * 16);
        uint32_t sw = off ^ ((uint32_t)(r & 7) << 4);
        cpa16(aB + sw, A + (size_t)(m0 + r) * K + kk + c * 8);
    }
#pragma unroll
    for (int i = 0; i < 8; i++) {
        int idx = tid + i * 128;
        int r = idx >> 3, c = idx & 7;
        uint32_t off = (uint32_t)(r * 128 + c * 16);
        uint32_t sw = off ^ ((uint32_t)(r & 7) << 4);
        cpa16(bB + sw, B + (size_t)(n0 + r) * K + kk + c * 8);
    }
}

template<int K, bool GELU>
__global__ void __launch_bounds__(128, 2) gemm_mma(
    const __half* __restrict__ A, int woff,
    const float* __restrict__ bias, int Ntot, __half* __restrict__ outH)
{
    extern __shared__ char smem[];
    uint32_t sb = smem_u32(smem);
    const int tid = threadIdx.x, wid = tid >> 5, lane = tid & 31;
    const int wm = wid & 1, wn = wid >> 1;
    const int m0 = blockIdx.y * 128, n0 = blockIdx.x * 128;
    constexpr int NT = K >> 6;
    const __half* W = g_w + woff;

    float acc[4][8][4];
#pragma unroll
    for (int i = 0; i < 4; i++)
#pragma unroll
        for (int j = 0; j < 8; j++)
#pragma unroll
            for (int kq = 0; kq < 4; kq++) acc[i][j][kq] = 0.f;

    load_tile(sb,         A, W, K, 0,  m0, n0, tid); CP_COMMIT();
    load_tile(sb + ST_SZ, A, W, K, 64, m0, n0, tid); CP_COMMIT();

    const int grp = lane >> 3, lr = lane & 7;
    const int a_row_b = wm * 64 + (grp & 1) * 8 + lr;
    const int a_kb    = (grp >> 1) * 16;
    const int b_row_b = wn * 64 + (grp >> 1) * 8 + lr;
    const int b_kb    = (grp & 1) * 16;

#pragma unroll
    for (int kt = 0; kt < NT; kt++) {
        const int s = kt % 3;
        if (kt + 1 == NT) { CP_WAIT0(); } else { CP_WAIT1(); }
        __syncthreads();
        if (kt + 2 < NT)
            load_tile(sb + ((kt + 2) % 3) * ST_SZ, A, W, K, (kt + 2) * 64, m0, n0, tid);
        CP_COMMIT();

        const uint32_t aBase = sb + s * ST_SZ;
        const uint32_t bBase = aBase + 16384;
#pragma unroll
        for (int ks = 0; ks < 4; ks++) {
            const int kb = ks * 32;
            uint32_t af[4][4];
#pragma unroll
            for (int mf = 0; mf < 4; mf++) {
                int row = a_row_b + mf * 16;
                uint32_t off = (uint32_t)(row * 128 + kb + a_kb);
                uint32_t addr = aBase + (off ^ ((uint32_t)(row & 7) << 4));
                ldm_x4(af[mf][0], af[mf][1], af[mf][2], af[mf][3], addr);
            }
            uint32_t bf[4][4];
#pragma unroll
            for (int np = 0; np < 4; np++) {
                int row = b_row_b + np * 16;
                uint32_t off = (uint32_t)(row * 128 + kb + b_kb);
                uint32_t addr = bBase + (off ^ ((uint32_t)(row & 7) << 4));
                ldm_x4(bf[np][0], bf[np][1], bf[np][2], bf[np][3], addr);
            }
#pragma unroll
            for (int mf = 0; mf < 4; mf++)
#pragma unroll
                for (int nf = 0; nf < 8; nf++)
                    mma_fp16(acc[mf][nf], af[mf], bf[nf >> 1][(nf & 1) * 2], bf[nf >> 1][(nf & 1) * 2 + 1]);
        }
    }

    const int qr = lane >> 2;
    const int qc = (lane & 3) * 2;
#pragma unroll
    for (int mf = 0; mf < 4; mf++) {
#pragma unroll
        for (int nf = 0; nf < 8; nf++) {
            int C = n0 + wn * 64 + nf * 8 + qc;
            float b0 = __ldg(&bias[C]), b1 = __ldg(&bias[C + 1]);
#pragma unroll
            for (int half_ = 0; half_ < 2; half_++) {
                int R = m0 + wm * 64 + mf * 16 + qr + half_ * 8;
                float v0 = acc[mf][nf][half_ * 2 + 0] + b0;
                float v1 = acc[mf][nf][half_ * 2 + 1] + b1;
                if (GELU) {
                    const float is2 = 0.70710678118654752f;
                    v0 = 0.5f * v0 * (1.0f + erff(v0 * is2));
                    v1 = 0.5f * v1 * (1.0f + erff(v1 * is2));
                }
                *(__half2*)&outH[(size_t)R * Ntot + C] = __floats2half2_rn(v0, v1);
            }
        }
    }
}

// ============== 8-warp GEMM (CTA 128x256, full row): proj(+LN2) / ffn2 =======
// 8 warps as 2(m) x 4(n), warp tile 64x64. One CTA owns complete output rows,
// enabling fused row-LayerNorm in the epilogue (proj) without extra kernels.
#define ST8_SZ   49152          // per stage: A 16KB + B 32KB
#define GEMM8_SMEM (3 * ST8_SZ) // 144KB

__device__ __forceinline__ void load_tile8(uint32_t stage_base,
    const __half* __restrict__ A, const __half* __restrict__ B,
    int K, int kk, int m0, int tid)
{
    uint32_t aB = stage_base;
    uint32_t bB = stage_base + 16384;
#pragma unroll
    for (int i = 0; i < 4; i++) {
        int idx = tid + i * 256;
        int r = idx >> 3, c = idx & 7;
        uint32_t off = (uint32_t)(r * 128 + c * 16);
        uint32_t sw = off ^ ((uint32_t)(r & 7) << 4);
        cpa16(aB + sw, A + (size_t)(m0 + r) * K + kk + c * 8);
    }
#pragma unroll
    for (int i = 0; i < 8; i++) {
        int idx = tid + i * 256;
        int r = idx >> 3, c = idx & 7;               // r 0..255
        uint32_t off = (uint32_t)(r * 128 + c * 16);
        uint32_t sw = off ^ ((uint32_t)(r & 7) << 4);
        cpa16(bB + sw, B + (size_t)r * K + kk + c * 8);
    }
}

template<int K, bool LNOUT>
__global__ void __launch_bounds__(256, 1) gemm8(
    const __half* __restrict__ A, int woff,
    const float* __restrict__ bias,
    float* __restrict__ outF, const float* __restrict__ resid,
    const float* __restrict__ lng, const float* __restrict__ lnb,
    __half* __restrict__ outH)
{
    extern __shared__ char smem[];
    uint32_t sb = smem_u32(smem);
    const int tid = threadIdx.x, wid = tid >> 5, lane = tid & 31;
    const int wm = wid & 1, wn = wid >> 1;          // 2 x 4 warp grid
    const int m0 = blockIdx.y * 128;
    constexpr int NT = K >> 6;
    const __half* W = g_w + woff;

    float acc[4][8][4];
#pragma unroll
    for (int i = 0; i < 4; i++)
#pragma unroll
        for (int j = 0; j < 8; j++)
#pragma unroll
            for (int kq = 0; kq < 4; kq++) acc[i][j][kq] = 0.f;

    load_tile8(sb,          A, W, K, 0,  m0, tid); CP_COMMIT();
    load_tile8(sb + ST8_SZ, A, W, K, 64, m0, tid); CP_COMMIT();

    const int grp = lane >> 3, lr = lane & 7;
    const int a_row_b = wm * 64 + (grp & 1) * 8 + lr;
    const int a_kb    = (grp >> 1) * 16;
    const int b_row_b = wn * 64 + (grp >> 1) * 8 + lr;
    const int b_kb    = (grp & 1) * 16;

#pragma unroll
    for (int kt = 0; kt < NT; kt++) {
        const int s = kt % 3;
        if (kt + 1 == NT) { CP_WAIT0(); } else { CP_WAIT1(); }
        __syncthreads();
        if (kt + 2 < NT)
            load_tile8(sb + ((kt + 2) % 3) * ST8_SZ, A, W, K, (kt + 2) * 64, m0, tid);
        CP_COMMIT();

        const uint32_t aBase = sb + s * ST8_SZ;
        const uint32_t bBase = aBase + 16384;
#pragma unroll
        for (int ks = 0; ks < 4; ks++) {
            const int kb = ks * 32;
            uint32_t af[4][4];
#pragma unroll
            for (int mf = 0; mf < 4; mf++) {
                int row = a_row_b + mf * 16;
                uint32_t off = (uint32_t)(row * 128 + kb + a_kb);
                uint32_t addr = aBase + (off ^ ((uint32_t)(row & 7) << 4));
                ldm_x4(af[mf][0], af[mf][1], af[mf][2], af[mf][3], addr);
            }
            uint32_t bf[4][4];
#pragma unroll
            for (int np = 0; np < 4; np++) {
                int row = b_row_b + np * 16;
                uint32_t off = (uint32_t)(row * 128 + kb + b_kb);
                uint32_t addr = bBase + (off ^ ((uint32_t)(row & 7) << 4));
                ldm_x4(bf[np][0], bf[np][1], bf[np][2], bf[np][3], addr);
            }
#pragma unroll
            for (int mf = 0; mf < 4; mf++)
#pragma unroll
                for (int nf = 0; nf < 8; nf++)
                    mma_fp16(acc[mf][nf], af[mf], bf[nf >> 1][(nf & 1) * 2], bf[nf >> 1][(nf & 1) * 2 + 1]);
        }
    }

    const int qr = lane >> 2;
    const int qc2 = (lane & 3) * 2;

    // ---- transform: acc := acc + bias + residual (full output value) ----
#pragma unroll
    for (int mf = 0; mf < 4; mf++)
#pragma unroll
        for (int nf = 0; nf < 8; nf++) {
            int C = wn * 64 + nf * 8 + qc2;
            float b0 = __ldg(&bias[C]), b1 = __ldg(&bias[C + 1]);
#pragma unroll
            for (int half_ = 0; half_ < 2; half_++) {
                int R = m0 + wm * 64 + mf * 16 + qr + half_ * 8;
                float2 rv = *(const float2*)&resid[(size_t)R * 256 + C];
                acc[mf][nf][half_ * 2 + 0] += b0 + rv.x;
                acc[mf][nf][half_ * 2 + 1] += b1 + rv.y;
            }
        }

    if (LNOUT) {
        // row LayerNorm fused: reduce across lanes (qc) then warps (wn)
        __syncthreads();                               // stages dead -> reuse smem
        float2* s_red = (float2*)smem;                 // [128 rows][4 wn]
        float2* s_mr  = (float2*)(smem + 4096);        // [128 rows] (mean, rstd)
#pragma unroll
        for (int mf = 0; mf < 4; mf++)
#pragma unroll
            for (int half_ = 0; half_ < 2; half_++) {
                float s1 = 0.f, s2 = 0.f;
#pragma unroll
                for (int nf = 0; nf < 8; nf++) {
                    float v0 = acc[mf][nf][half_ * 2], v1 = acc[mf][nf][half_ * 2 + 1];
                    s1 += v0 + v1; s2 += v0 * v0 + v1 * v1;
                }
                s1 += __shfl_xor_sync(0xffffffffu, s1, 1);
                s2 += __shfl_xor_sync(0xffffffffu, s2, 1);
                s1 += __shfl_xor_sync(0xffffffffu, s1, 2);
                s2 += __shfl_xor_sync(0xffffffffu, s2, 2);
                if ((lane & 3) == 0) {
                    int rloc = wm * 64 + mf * 16 + half_ * 8 + qr;
                    s_red[rloc * 4 + wn] = make_float2(s1, s2);
                }
            }
        __syncthreads();
        if (tid < 128) {
            float s1 = 0.f, s2 = 0.f;
#pragma unroll
            for (int w = 0; w < 4; w++) { float2 p = s_red[tid * 4 + w]; s1 += p.x; s2 += p.y; }
            float mean = s1 * (1.f / 256.f);
            float var = s2 * (1.f / 256.f) - mean * mean;
            s_mr[tid] = make_float2(mean, rsqrtf(var + 1e-5f));
        }
        __syncthreads();
#pragma unroll
        for (int mf = 0; mf < 4; mf++)
#pragma unroll
            for (int half_ = 0; half_ < 2; half_++) {
                int rloc = wm * 64 + mf * 16 + half_ * 8 + qr;
                float2 mr = s_mr[rloc];
                int R = m0 + rloc;
#pragma unroll
                for (int nf = 0; nf < 8; nf++) {
                    int C = wn * 64 + nf * 8 + qc2;
                    float v0 = acc[mf][nf][half_ * 2], v1 = acc[mf][nf][half_ * 2 + 1];
                    size_t gidx = (size_t)R * 256 + C;
                    *(float2*)&outF[gidx] = make_float2(v0, v1);
                    float g0 = __ldg(&lng[C]), g1 = __ldg(&lng[C + 1]);
                    float bb0 = __ldg(&lnb[C]), bb1 = __ldg(&lnb[C + 1]);
                    float y0 = (v0 - mr.x) * mr.y * g0 + bb0;
                    float y1 = (v1 - mr.x) * mr.y * g1 + bb1;
                    *(__half2*)&outH[gidx] = __floats2half2_rn(y0, y1);
                }
            }
    } else {
#pragma unroll
        for (int mf = 0; mf < 4; mf++)
#pragma unroll
            for (int nf = 0; nf < 8; nf++) {
                int C = wn * 64 + nf * 8 + qc2;
#pragma unroll
                for (int half_ = 0; half_ < 2; half_++) {
                    int R = m0 + wm * 64 + mf * 16 + qr + half_ * 8;
                    *(float2*)&outF[(size_t)R * 256 + C] =
                        make_float2(acc[mf][nf][half_ * 2], acc[mf][nf][half_ * 2 + 1]);
                }
            }
    }
}

// ---------------- tensor-core attention: CTA per sequence, warp = head -------
#define ATTN_SMEM 49152
__device__ __forceinline__ uint32_t swz(int row, int byte_) {
    return (uint32_t)((row * 64 + byte_) ^ ((row & 3) << 4));
}
__global__ void __launch_bounds__(256, 2) attn_kernel(const float* __restrict__ logit_scale) {
    extern __shared__ char smem[];
    uint32_t sb = smem_u32(smem);
    const int tid = threadIdx.x, hd = tid >> 5, lane = tid & 31;
    const size_t n = blockIdx.x;

#pragma unroll
    for (int i = 0; i < 12; i++) {
        int idx = tid + i * 256;
        int c16 = idx & 3, h = (idx >> 2) & 7, r = (idx >> 5) & 31, w = idx >> 10;
        uint32_t dst = sb + (uint32_t)(h * 3 + w) * 2048 + swz(r, c16 * 16);
        if (r < 25) {
            const __half* src = g_qkv + (n * 25 + r) * 768 + w * 256 + h * 32 + c16 * 8;
            uint4 v = *(const uint4*)src;
            asm volatile("st.shared.v4.b32 [%0], {%1,%2,%3,%4};" :: "r"(dst), "r"(v.x), "r"(v.y), "r"(v.z), "r"(v.w));
        } else {
            asm volatile("st.shared.v4.b32 [%0], {%1,%1,%1,%1};" :: "r"(dst), "r"(0u));
        }
    }
    __syncthreads();

    const uint32_t qb = sb + (uint32_t)hd * 3 * 2048;
    const uint32_t kb = qb + 2048;
    const uint32_t vb = qb + 4096;
    const int grp = lane >> 3, lr = lane & 7;
    const int qr = lane >> 2, qc = lane & 3;

    uint32_t af[2][2][4];
#pragma unroll
    for (int mf = 0; mf < 2; mf++)
#pragma unroll
        for (int ks = 0; ks < 2; ks++) {
            int row = mf * 16 + (grp & 1) * 8 + lr;
            uint32_t addr = qb + swz(row, (grp >> 1) * 16 + ks * 32);
            ldm_x4(af[mf][ks][0], af[mf][ks][1], af[mf][ks][2], af[mf][ks][3], addr);
        }
    uint32_t kf[2][2][4];
#pragma unroll
    for (int np = 0; np < 2; np++)
#pragma unroll
        for (int ks = 0; ks < 2; ks++) {
            int row = np * 16 + (grp >> 1) * 8 + lr;
            uint32_t addr = kb + swz(row, (grp & 1) * 16 + ks * 32);
            ldm_x4(kf[np][ks][0], kf[np][ks][1], kf[np][ks][2], kf[np][ks][3], addr);
        }

    float acc[2][4][4];
#pragma unroll
    for (int mf = 0; mf < 2; mf++)
#pragma unroll
        for (int nf = 0; nf < 4; nf++)
#pragma unroll
            for (int u = 0; u < 4; u++) acc[mf][nf][u] = 0.f;
#pragma unroll
    for (int ks = 0; ks < 2; ks++)
#pragma unroll
        for (int mf = 0; mf < 2; mf++)
#pragma unroll
            for (int nf = 0; nf < 4; nf++)
                mma_fp16(acc[mf][nf], af[mf][ks], kf[nf >> 1][ks][(nf & 1) * 2], kf[nf >> 1][ks][(nf & 1) * 2 + 1]);

    const float LOG100 = 4.6051701859880914f;
    const float stot = __expf(fminf(__ldg(&logit_scale[hd]), LOG100)) * 0.17677669529663687f;

    float nqp[4], nkp[4];
#pragma unroll
    for (int i = 0; i < 4; i++) {
        int mf = i >> 1, h2 = i & 1;
        nqp[i] = hsq(af[mf][0][h2]) + hsq(af[mf][0][h2 + 2]) + hsq(af[mf][1][h2]) + hsq(af[mf][1][h2 + 2]);
    }
#pragma unroll
    for (int i = 0; i < 4; i++) {
        int np = i >> 1, t = i & 1;
        nkp[i] = hsq(kf[np][0][2 * t]) + hsq(kf[np][0][2 * t + 1]) + hsq(kf[np][1][2 * t]) + hsq(kf[np][1][2 * t + 1]);
    }
#pragma unroll
    for (int o = 1; o <= 2; o <<= 1) {
#pragma unroll
        for (int i = 0; i < 4; i++) {
            nqp[i] += __shfl_xor_sync(0xffffffffu, nqp[i], o);
            nkp[i] += __shfl_xor_sync(0xffffffffu, nkp[i], o);
        }
    }
    float nqr4[4], nkr4[4];
#pragma unroll
    for (int i = 0; i < 4; i++) {
        nqr4[i] = stot / fmaxf(sqrtf(nqp[i]), 1e-12f);
        nkr4[i] = 1.0f / fmaxf(sqrtf(nkp[i]), 1e-12f);
    }
    float skc[4][2];
#pragma unroll
    for (int nf = 0; nf < 4; nf++)
#pragma unroll
        for (int u = 0; u < 2; u++)
            skc[nf][u] = __shfl_sync(0xffffffffu, nkr4[nf], ((2 * qc + u) & 7) << 2);

#pragma unroll
    for (int mf = 0; mf < 2; mf++)
#pragma unroll
        for (int h2 = 0; h2 < 2; h2++) {
            float sq_ = nqr4[mf * 2 + h2];
            float vals[8];
#pragma unroll
            for (int nf = 0; nf < 4; nf++)
#pragma unroll
                for (int u = 0; u < 2; u++) {
                    float v = acc[mf][nf][h2 * 2 + u] * sq_ * skc[nf][u];
                    if (nf == 3 && (24 + 2 * qc + u) >= 25) v = -1e30f;
                    vals[nf * 2 + u] = v;
                }
            float m = vals[0];
#pragma unroll
            for (int j = 1; j < 8; j++) m = fmaxf(m, vals[j]);
            m = fmaxf(m, __shfl_xor_sync(0xffffffffu, m, 1));
            m = fmaxf(m, __shfl_xor_sync(0xffffffffu, m, 2));
            float s = 0.f;
#pragma unroll
            for (int j = 0; j < 8; j++) { vals[j] = __expf(vals[j] - m); s += vals[j]; }
            s += __shfl_xor_sync(0xffffffffu, s, 1);
            s += __shfl_xor_sync(0xffffffffu, s, 2);
            float inv = 1.0f / s;
#pragma unroll
            for (int nf = 0; nf < 4; nf++)
#pragma unroll
                for (int u = 0; u < 2; u++)
                    acc[mf][nf][h2 * 2 + u] = vals[nf * 2 + u] * inv;
        }

    uint32_t pa[2][2][4];
#pragma unroll
    for (int mf = 0; mf < 2; mf++)
#pragma unroll
        for (int ks = 0; ks < 2; ks++) {
            __half2 h0 = __floats2half2_rn(acc[mf][2 * ks][0], acc[mf][2 * ks][1]);
            __half2 h1 = __floats2half2_rn(acc[mf][2 * ks][2], acc[mf][2 * ks][3]);
            __half2 h2_ = __floats2half2_rn(acc[mf][2 * ks + 1][0], acc[mf][2 * ks + 1][1]);
            __half2 h3 = __floats2half2_rn(acc[mf][2 * ks + 1][2], acc[mf][2 * ks + 1][3]);
            pa[mf][ks][0] = *(uint32_t*)&h0; pa[mf][ks][1] = *(uint32_t*)&h1;
            pa[mf][ks][2] = *(uint32_t*)&h2_; pa[mf][ks][3] = *(uint32_t*)&h3;
        }

    uint32_t vf[2][2][4];
#pragma unroll
    for (int ks = 0; ks < 2; ks++)
#pragma unroll
        for (int np = 0; np < 2; np++) {
            int row = ks * 16 + (grp & 1) * 8 + lr;
            uint32_t addr = vb + swz(row, (grp >> 1) * 16 + np * 32);
            ldm_x4_t(vf[ks][np][0], vf[ks][np][1], vf[ks][np][2], vf[ks][np][3], addr);
        }

    float oacc[2][4][4];
#pragma unroll
    for (int mf = 0; mf < 2; mf++)
#pragma unroll
        for (int nf = 0; nf < 4; nf++)
#pragma unroll
            for (int u = 0; u < 4; u++) oacc[mf][nf][u] = 0.f;
#pragma unroll
    for (int ks = 0; ks < 2; ks++)
#pragma unroll
        for (int mf = 0; mf < 2; mf++)
#pragma unroll
            for (int nf = 0; nf < 4; nf++)
                mma_fp16(oacc[mf][nf], pa[mf][ks], vf[ks][nf >> 1][(nf & 1) * 2], vf[ks][nf >> 1][(nf & 1) * 2 + 1]);

#pragma unroll
    for (int mf = 0; mf < 2; mf++)
#pragma unroll
        for (int h2 = 0; h2 < 2; h2++) {
            int R = mf * 16 + h2 * 8 + qr;
            if (R < 25) {
#pragma unroll
                for (int nf = 0; nf < 4; nf++) {
                    int d = nf * 8 + 2 * qc;
                    __half2 hv = __floats2half2_rn(oacc[mf][nf][h2 * 2], oacc[mf][nf][h2 * 2 + 1]);
                    *(__half2*)&g_a[(n * 25 + R) * 256 + hd * 32 + d] = hv;
                }
            }
        }
}

// ---------------- launch -----------------------------------------------------
extern "C" void kernel_launch(void* const* d_in, const int* in_sizes, int n_in,
                              void* d_out, int out_size)
{
    const float* x           = (const float*)d_in[0];
    const float* ln1_g       = (const float*)d_in[1];
    const float* ln1_b       = (const float*)d_in[2];
    const float* qkv_w       = (const float*)d_in[3];
    const float* qkv_b       = (const float*)d_in[4];
    const float* proj_w      = (const float*)d_in[5];
    const float* proj_b      = (const float*)d_in[6];
    const float* logit_scale = (const float*)d_in[7];
    const float* ln2_g       = (const float*)d_in[8];
    const float* ln2_b       = (const float*)d_in[9];
    const float* ffn_w1      = (const float*)d_in[10];
    const float* ffn_b1      = (const float*)d_in[11];
    const float* ffn_w2      = (const float*)d_in[12];
    const float* ffn_b2      = (const float*)d_in[13];
    float* out = (float*)d_out;

    cudaFuncSetAttribute(gemm_mma<256,false>, cudaFuncAttributeMaxDynamicSharedMemorySize, GEMM_SMEM);
    cudaFuncSetAttribute(gemm_mma<256,true >, cudaFuncAttributeMaxDynamicSharedMemorySize, GEMM_SMEM);
    cudaFuncSetAttribute(gemm8<256 ,true >,  cudaFuncAttributeMaxDynamicSharedMemorySize, GEMM8_SMEM);
    cudaFuncSetAttribute(gemm8<1024,false>,  cudaFuncAttributeMaxDynamicSharedMemorySize, GEMM8_SMEM);
    cudaFuncSetAttribute(attn_kernel, cudaFuncAttributeMaxDynamicSharedMemorySize, ATTN_SMEM);

    __half *ap, *qkvp, *hp;
    cudaGetSymbolAddress((void**)&ap,   g_a);
    cudaGetSymbolAddress((void**)&qkvp, g_qkv);
    cudaGetSymbolAddress((void**)&hp,   g_h);

    // 1) weight transpose -> fp16
    prep_w_kernel<<<3072, 256>>>(qkv_w, proj_w, ffn_w1, ffn_w2);
    // 2) LN1 -> fp16 activations
    ln_h_kernel<<<M_TOT / 8, 256>>>(x, ln1_g, ln1_b);
    // 3) QKV GEMM -> g_qkv (fp16)
    gemm_mma<256,false><<<dim3(6, 1600), 128, GEMM_SMEM>>>(
        ap, WOFF_QKV, qkv_b, 768, qkvp);
    // 4) attention -> g_a (fp16)
    attn_kernel<<<NSEQ, 256, ATTN_SMEM>>>(logit_scale);
    // 5) proj GEMM + residual(x) + fused LN2 -> out (fp32) and g_a (LN2 fp16)
    gemm8<256,true><<<dim3(1, 1600), 256, GEMM8_SMEM>>>(
        ap, WOFF_PROJ, proj_b, out, x, ln2_g, ln2_b, ap);
    // 6) FFN1 GEMM + GELU -> g_h (fp16)
    gemm_mma<256,true><<<dim3(8, 1600), 128, GEMM_SMEM>>>(
        ap, WOFF_F1, ffn_b1, 1024, hp);
    // 7) FFN2 GEMM + residual(out) -> out (final)
    gemm8<1024,false><<<dim3(1, 1600), 256, GEMM8_SMEM>>>(
        hp, WOFF_F2, ffn_b2, out, out, nullptr, nullptr, nullptr);
}